// round 15
// baseline (speedup 1.0000x reference)
#include <cuda_runtime.h>
#include <cuda_bf16.h>

// Problem constants (fixed shapes from setup_inputs):
// B=32, S1=14, S2=14, NC=2, DC=16, F=32, I=8
#define NROWS   200704      // 32*14*14*2*16  (one row = (b,s1,s2,nc,dc))
#define FDIM    32
#define IDIM    8
#define NCDC    32          // NC*DC
#define NOUT    51380224    // NROWS * F * I  (elements of C; U_hat_I same size)

// Precomputed max_f W_t[ncdc, f, i]  (256 values). diag >= 0 so the softmax
// max factors out: max_f(diag*Wt) = diag * max_f(Wt).
__device__ float g_wtmax[NCDC * IDIM];

__global__ void wtmax_kernel(const float* __restrict__ W_t) {
    int t = threadIdx.x;            // 0..255 : ncdc*8 + i
    int ncdc = t >> 3;
    int i    = t & 7;
    const float* base = W_t + ncdc * (FDIM * IDIM) + i;
    float m = base[0];
#pragma unroll
    for (int f = 1; f < FDIM; f++) m = fmaxf(m, base[f * IDIM]);
    g_wtmax[t] = m;
}

__global__ __launch_bounds__(256, 8) void msa_kernel(
    const float* __restrict__ U_hat,     // [NROWS, 32]
    const float* __restrict__ W_t,       // [NCDC, 32, 8]
    const float* __restrict__ W_affine,  // [NCDC, 32, 8]
    float* __restrict__ out)             // [NOUT] = C, [NOUT..2*NOUT) = U_hat_I
{
    const int row  = blockIdx.x * 8 + (threadIdx.x >> 5);   // one warp per row
    const int lane = threadIdx.x & 31;                      // lane == f
    if (row >= NROWS) return;

    const int ncdc = row & 31;   // row % (NC*DC): nc,dc are the fastest row dims

    // ---- loads (all coalesced: lane f touches base + f*32 bytes) ----
    const float u = __ldg(U_hat + row * FDIM + lane);

    const float4* wa4 = reinterpret_cast<const float4*>(
        W_affine + ncdc * (FDIM * IDIM) + lane * IDIM);
    const float4* wt4 = reinterpret_cast<const float4*>(
        W_t + ncdc * (FDIM * IDIM) + lane * IDIM);
    float4 wa0 = __ldg(wa4), wa1 = __ldg(wa4 + 1);
    float4 wt0 = __ldg(wt4), wt1 = __ldg(wt4 + 1);

    float wa[IDIM] = {wa0.x, wa0.y, wa0.z, wa0.w, wa1.x, wa1.y, wa1.z, wa1.w};
    float wt[IDIM] = {wt0.x, wt0.y, wt0.z, wt0.w, wt1.x, wt1.y, wt1.z, wt1.w};

    // ---- U_hat_I and per-i squared-norm partials ----
    float uI[IDIM], p[IDIM];
#pragma unroll
    for (int i = 0; i < IDIM; i++) {
        uI[i] = u * wa[i];
        p[i]  = uI[i] * uI[i];
    }

    // butterfly sum over lanes (= over f) for each of the 8 i's
#pragma unroll
    for (int off = 16; off > 0; off >>= 1) {
#pragma unroll
        for (int i = 0; i < IDIM; i++)
            p[i] += __shfl_xor_sync(0xFFFFFFFFu, p[i], off);
    }

    // diag[i] = sum_f uI^2 / sqrt(16);  softmax max = diag * max_f(Wt)
    float e[IDIM];
#pragma unroll
    for (int i = 0; i < IDIM; i++) {
        float diag = p[i] * 0.25f;
        float m    = diag * g_wtmax[ncdc * IDIM + i];
        e[i] = __expf(fmaf(diag, wt[i], -m));   // exp(diag*Wt[f,i] - max)
    }

    // butterfly sum of exps over lanes (= over f)
    float s[IDIM];
#pragma unroll
    for (int i = 0; i < IDIM; i++) s[i] = e[i];
#pragma unroll
    for (int off = 16; off > 0; off >>= 1) {
#pragma unroll
        for (int i = 0; i < IDIM; i++)
            s[i] += __shfl_xor_sync(0xFFFFFFFFu, s[i], off);
    }

    float c[IDIM];
#pragma unroll
    for (int i = 0; i < IDIM; i++) c[i] = e[i] * __frcp_rn(s[i]);

    // ---- stores: lane f writes 8 contiguous floats at (row, f, :) ----
    const long long base = (long long)row * (FDIM * IDIM) + lane * IDIM;
    float4* co = reinterpret_cast<float4*>(out + base);
    co[0] = make_float4(c[0], c[1], c[2], c[3]);
    co[1] = make_float4(c[4], c[5], c[6], c[7]);

    float4* uo = reinterpret_cast<float4*>(out + (long long)NOUT + base);
    uo[0] = make_float4(uI[0], uI[1], uI[2], uI[3]);
    uo[1] = make_float4(uI[4], uI[5], uI[6], uI[7]);
}

extern "C" void kernel_launch(void* const* d_in, const int* in_sizes, int n_in,
                              void* d_out, int out_size) {
    // metadata order: U_hat (6,422,528), W_t (8,192), W_affine (8,192).
    // Robustness: pick the largest input as U_hat; keep W_t before W_affine.
    int iu = 0;
    for (int k = 1; k < n_in; k++)
        if (in_sizes[k] > in_sizes[iu]) iu = k;
    int iw[2], nw = 0;
    for (int k = 0; k < n_in && nw < 2; k++)
        if (k != iu) iw[nw++] = k;

    const float* U_hat    = (const float*)d_in[iu];
    const float* W_t      = (const float*)d_in[iw[0]];
    const float* W_affine = (const float*)d_in[iw[1]];
    float* out = (float*)d_out;

    wtmax_kernel<<<1, 256>>>(W_t);

    const int warps_per_block = 8;
    const int blocks = (NROWS + warps_per_block - 1) / warps_per_block; // 25088
    msa_kernel<<<blocks, 256>>>(U_hat, W_t, W_affine, out);
}

// round 17
// speedup vs baseline: 1.3374x; 1.3374x over previous
#include <cuda_runtime.h>

// Shapes (fixed): B=32, S1=S2=14, NC=2, DC=16, F=32, I=8
// row = (b,s1,s2,nc,dc): NROWS = 200704, row % 32 == ncdc (nc,dc fastest dims)
#define NROWS   200704
#define FDIM    32
#define IDIM    8
#define NCDC    32
#define OUTER   6272          // NROWS / NCDC
#define RPW     8             // rows per warp (same ncdc, stride-32 rows)
#define NOUT    51380224LL    // NROWS * F * I

// Fold-exchange warp reduction: v[8] per lane -> out[i] = sum over all 32
// lanes of v[lane][i], broadcast to every lane. 17 SHFL (vs 40 butterfly).
// Stages fold the i-dimension into lane bits 4,3,2; two butterfly stages
// (xor 1, xor 2) complete the f-sum; lane (i<<2) then holds sum for i.
__device__ __forceinline__ void warp_reduce8(const float* __restrict__ v,
                                             float* __restrict__ out,
                                             int lane) {
    const bool b4 = lane & 16, b3 = lane & 8, b2 = lane & 4;
    float q[4];
#pragma unroll
    for (int j = 0; j < 4; j++) {
        float send = b4 ? v[j]     : v[j + 4];
        float keep = b4 ? v[j + 4] : v[j];
        q[j] = keep + __shfl_xor_sync(0xFFFFFFFFu, send, 16);
    }
    float r[2];
#pragma unroll
    for (int j = 0; j < 2; j++) {
        float send = b3 ? q[j]     : q[j + 2];
        float keep = b3 ? q[j + 2] : q[j];
        r[j] = keep + __shfl_xor_sync(0xFFFFFFFFu, send, 8);
    }
    float send = b2 ? r[0] : r[1];
    float keep = b2 ? r[1] : r[0];
    float s = keep + __shfl_xor_sync(0xFFFFFFFFu, send, 4);
    s += __shfl_xor_sync(0xFFFFFFFFu, s, 1);
    s += __shfl_xor_sync(0xFFFFFFFFu, s, 2);
    // lane holds the full sum for i = (lane>>2)&7; broadcast all 8
#pragma unroll
    for (int i = 0; i < IDIM; i++)
        out[i] = __shfl_sync(0xFFFFFFFFu, s, i << 2);
}

__global__ __launch_bounds__(256, 4) void msa_kernel(
    const float* __restrict__ U_hat,     // [NROWS, 32]
    const float* __restrict__ W_t,       // [NCDC, 32, 8]
    const float* __restrict__ W_affine,  // [NCDC, 32, 8]
    float* __restrict__ out)             // [0,NOUT)=C  [NOUT,2*NOUT)=U_hat_I
{
    const int warp = blockIdx.x * 8 + (threadIdx.x >> 5);   // 0..25087
    const int lane = threadIdx.x & 31;                      // lane == f
    const int ncdc = warp & 31;            // this warp's fixed (nc,dc)
    const int outer0 = (warp >> 5) * RPW;  // first outer index of its 8 rows

    // ---- weights: loaded ONCE per warp, amortized over 8 rows ----
    const float4* wa4 = reinterpret_cast<const float4*>(
        W_affine + ncdc * (FDIM * IDIM) + lane * IDIM);
    const float4* wt4 = reinterpret_cast<const float4*>(
        W_t + ncdc * (FDIM * IDIM) + lane * IDIM);
    const float4 a0 = __ldg(wa4), a1 = __ldg(wa4 + 1);
    const float4 t0 = __ldg(wt4), t1 = __ldg(wt4 + 1);
    const float wa[IDIM] = {a0.x, a0.y, a0.z, a0.w, a1.x, a1.y, a1.z, a1.w};
    const float wt[IDIM] = {t0.x, t0.y, t0.z, t0.w, t1.x, t1.y, t1.z, t1.w};

    // wq[i] = 0.25*(wt[f,i] - max_f wt[f,i]), once per warp.
    // diag >= 0, so softmax max factors out: exp(d*wt - d*wm) = exp(P*wq)
    // where P is the raw squared-norm sum and d = P/sqrt(16) = P/4.
    float wq[IDIM];
#pragma unroll
    for (int i = 0; i < IDIM; i++) {
        float m = wt[i];
#pragma unroll
        for (int off = 16; off > 0; off >>= 1)
            m = fmaxf(m, __shfl_xor_sync(0xFFFFFFFFu, m, off));
        wq[i] = 0.25f * (wt[i] - m);
    }

    // ---- all 8 U_hat scalars up-front: MLP=8 hides DRAM latency ----
    float u[RPW];
#pragma unroll
    for (int k = 0; k < RPW; k++) {
        const int row = (outer0 + k) * NCDC + ncdc;
        u[k] = __ldcs(U_hat + row * FDIM + lane);   // coalesced, streaming
    }

#pragma unroll
    for (int k = 0; k < RPW; k++) {
        float uI[IDIM], p[IDIM];
#pragma unroll
        for (int i = 0; i < IDIM; i++) {
            uI[i] = u[k] * wa[i];
            p[i]  = uI[i] * uI[i];
        }

        float P[IDIM];                      // P[i] = sum_f uI^2
        warp_reduce8(p, P, lane);

        float e[IDIM];
#pragma unroll
        for (int i = 0; i < IDIM; i++)
            e[i] = __expf(P[i] * wq[i]);    // exp(diag*Wt - diag*max)

        float s[IDIM];                      // softmax denominator
        warp_reduce8(e, s, lane);

        float c[IDIM];
#pragma unroll
        for (int i = 0; i < IDIM; i++)
            c[i] = __fdividef(e[i], s[i]);

        // ---- stores: lane f owns 8 contiguous floats of (row, f, :) ----
        const long long row  = (long long)(outer0 + k) * NCDC + ncdc;
        const long long base = row * (FDIM * IDIM) + lane * IDIM;
        __stcs(reinterpret_cast<float4*>(out + base),
               make_float4(c[0], c[1], c[2], c[3]));
        __stcs(reinterpret_cast<float4*>(out + base) + 1,
               make_float4(c[4], c[5], c[6], c[7]));
        __stcs(reinterpret_cast<float4*>(out + NOUT + base),
               make_float4(uI[0], uI[1], uI[2], uI[3]));
        __stcs(reinterpret_cast<float4*>(out + NOUT + base) + 1,
               make_float4(uI[4], uI[5], uI[6], uI[7]));
    }
}

extern "C" void kernel_launch(void* const* d_in, const int* in_sizes, int n_in,
                              void* d_out, int out_size) {
    // metadata order: U_hat (6,422,528), W_t (8,192), W_affine (8,192).
    // Pick largest input as U_hat; remaining two keep their relative order.
    int iu = 0;
    for (int k = 1; k < n_in; k++)
        if (in_sizes[k] > in_sizes[iu]) iu = k;
    int iw[2], nw = 0;
    for (int k = 0; k < n_in && nw < 2; k++)
        if (k != iu) iw[nw++] = k;

    const float* U_hat    = (const float*)d_in[iu];
    const float* W_t      = (const float*)d_in[iw[0]];
    const float* W_affine = (const float*)d_in[iw[1]];
    float* out = (float*)d_out;

    // 25088 warps total: 784 outer-chunks x 32 ncdc; 8 warps per block
    const int blocks = (OUTER / RPW) * NCDC / 8;   // 3136
    msa_kernel<<<blocks, 256>>>(U_hat, W_t, W_affine, out);
}